// round 12
// baseline (speedup 1.0000x reference)
#include <cuda_runtime.h>
#include <cuda_bf16.h>
#include <cstdint>

// ---------------- Problem constants ----------------
#define BDIM 128
#define HDIM 4
#define WDIM 64
#define CDIM 16
#define FEAT (HDIM*WDIM*CDIM)   // 4096

// Output layout (floats): [sat 524288][grd 524288][distance 16384 (g,s)][orien 16384 (s,g)]
#define OFF_SAT   0
#define OFF_GRD   (BDIM*FEAT)
#define OFF_DIST  (2*BDIM*FEAT)
#define OFF_OR    (2*BDIM*FEAT + BDIM*BDIM)

// A (satC): rows cr=c*4+h (64 rows) of w'=0..126. k = cr*64 + kw. Full fp32 in smem.
#define ROW_W 127
#define A_FLOATS (64*ROW_W)     // 8128

// ---------------- Static device scratch ----------------
// grd transposed + (k,k+4) pair-interleaved, in k32 groups of 16 rows:
// idx = ((ch32*16 + q*4 + r)*256) + g*2 + half;  k = ch32*32 + q*8 + r + half*4
__device__ float g_grdH2[4096*BDIM];
__device__ float g_grdL2[4096*BDIM];

// ---------------- SMEM layout ----------------
constexpr int TERM     = 32*264;              // 8448 floats: 32 k-pair rows x (128 g-pairs + pad)
constexpr int BUFF     = 2*TERM;              // 16896 floats per k64 chunk buffer (hi+lo)
constexpr int SMEM_BYTES = (A_FLOATS + 2*BUFF)*4;   // 167680 B

// ---------------- PTX helpers (sm_80-baseline only) ----------------
__device__ __forceinline__ void cp16(float* smem_dst, const float* gsrc) {
    unsigned sa = (unsigned)__cvta_generic_to_shared(smem_dst);
    asm volatile("cp.async.cg.shared.global [%0], [%1], 16;\n" :: "r"(sa), "l"(gsrc));
}
#define CP_COMMIT() asm volatile("cp.async.commit_group;\n" ::: "memory")
#define CP_WAIT0()  asm volatile("cp.async.wait_group 0;\n" ::: "memory")
#define CP_WAIT1()  asm volatile("cp.async.wait_group 1;\n" ::: "memory")

__device__ __forceinline__ float tf32r(float x) {
    unsigned r;
    asm("cvt.rna.tf32.f32 %0, %1;" : "=r"(r) : "f"(x));
    return __uint_as_float(r);
}
__device__ __forceinline__ void split2(float af, unsigned& hi, unsigned& lo) {
    unsigned h = __float_as_uint(af) & 0xFFFFE000u;      // exact tf32 hi
    hi = h;
    lo = __float_as_uint(tf32r(af - __uint_as_float(h)));
}
__device__ __forceinline__ void mma8(float* d, const unsigned* a, const unsigned* b) {
    asm("mma.sync.aligned.m16n8k8.row.col.f32.tf32.tf32.f32 "
        "{%0,%1,%2,%3},{%4,%5,%6,%7},{%8,%9},{%0,%1,%2,%3};"
        : "+f"(d[0]), "+f"(d[1]), "+f"(d[2]), "+f"(d[3])
        : "r"(a[0]), "r"(a[1]), "r"(a[2]), "r"(a[3]), "r"(b[0]), "r"(b[1]));
}

// ---------------- Pre-kernel: grd split (pair-interleaved transpose) + echo ----------------
__global__ void grdsplit_kernel(const float* __restrict__ grd, float* __restrict__ grd_echo)
{
    int j = blockIdx.x * 256 + threadIdx.x;   // 0..524287
    int half = j & 1;
    int g    = (j >> 1) & 127;
    int row  = (j >> 8) & 15;
    int ch   = j >> 12;
    int q = row >> 2, rr = row & 3;
    int kg = ch*32 + q*8 + rr + half*4;
    int c  = kg >> 8, h = (kg >> 6) & 3, kwf = kg & 63;
    int src = ((g*HDIM + h)*WDIM + kwf)*CDIM + c;
    float v  = __ldg(&grd[src]);
    float hi = __uint_as_float(__float_as_uint(v) & 0xFFFFE000u);
    g_grdH2[j] = hi;
    g_grdL2[j] = tf32r(v - hi);
    grd_echo[src] = v;
}

// ---------------- Main kernel: block per s, 256 threads = 8 warps ----------------
// warp w: mrow=(w&1)*32 (j), ncol=(w>>1)*32 (g). Warp tile m32 n32, full K.
// 64 chunks of k64; 2-buffer cp.async B; sliding-window A (2 new LDS per q);
// B frag ping-pong prefetch; hi/lo of A derived in registers (bit-identical split).
__global__ __launch_bounds__(256, 1)
void corr_mma_kernel(const float* __restrict__ sat,
                     float* __restrict__ dist, float* __restrict__ orien)
{
    extern __shared__ float smem[];
    float* Af   = smem;                  // 8128 fp32: [cr][w']
    float* bufs = smem + A_FLOATS;

    const int s  = blockIdx.x;
    const int t  = threadIdx.x;
    const int w  = t >> 5;
    const int l  = t & 31;
    const int mrow = (w & 1) * 32;
    const int ncol = (w >> 1) * 32;

    const int alane  = (l >> 2) + (l & 3);
    const int blane2 = (ncol + (l >> 2)) * 2;

    __shared__ float s_warp[8];
    __shared__ float s_norm;

    // stage one k64 chunk (= 32 interleaved rows per term) via cp.async
    auto stageB = [&](int ch, float* dstbuf) {
        #pragma unroll
        for (int i = 0; i < 16; ++i) {
            int idx = i*256 + t;                 // 4096 = 2 terms x 32 rows x 64 units
            int term = idx >> 11;
            int ru = idx & 2047;
            int row = ru >> 6, u = ru & 63;
            const float* src = (term ? g_grdL2 : g_grdH2) + ch*8192 + row*256 + u*4;
            cp16(dstbuf + term*TERM + row*264 + u*4, src);
        }
    };
    stageB(0, bufs);        CP_COMMIT();
    stageB(1, bufs + BUFF); CP_COMMIT();

    // ---- prologue: stage A (fp32, circular-extended, [cr][w']) + norm ----
    {
        const float* satb = sat + s * FEAT;
        float ss = 0.f;
        #pragma unroll
        for (int it = 0; it < 4; ++it) {
            int i  = it*256 + t;                 // 1024 float4 ids
            int c4 = i & 3;
            int wI = (i >> 2) & 63;
            int h  = i >> 8;
            float4 v = __ldg((const float4*)(satb + h*WDIM*CDIM + wI*CDIM + c4*4));
            float vv[4] = {v.x, v.y, v.z, v.w};
            #pragma unroll
            for (int jc = 0; jc < 4; ++jc) {
                int cr = (c4*4 + jc)*4 + h;
                Af[cr*ROW_W + wI] = vv[jc];
                if (wI < WDIM-1) Af[cr*ROW_W + wI + WDIM] = vv[jc];
                ss += vv[jc]*vv[jc];
            }
        }
        #pragma unroll
        for (int o = 16; o > 0; o >>= 1) ss += __shfl_down_sync(0xffffffffu, ss, o);
        if (l == 0) s_warp[w] = ss;
    }
    __syncthreads();                             // Af + s_warp visible; chunk cp.async in flight
    if (t == 0) {
        float tot = 0.f;
        #pragma unroll
        for (int i = 0; i < 8; ++i) tot += s_warp[i];
        s_norm = fmaxf(sqrtf(tot), 1e-12f);      // consumed only after later barriers
    }

    float acc[2][4][4];
    #pragma unroll
    for (int f = 0; f < 2; ++f)
        #pragma unroll
        for (int n = 0; n < 4; ++n)
            #pragma unroll
            for (int r = 0; r < 4; ++r) acc[f][n][r] = 0.f;

    auto loadB = [&](const float* bm, int q, unsigned* h8, unsigned* l8) {
        const float* bp = bm + (q*4 + (l & 3))*264 + blane2;
        #pragma unroll
        for (int n = 0; n < 4; ++n) {
            unsigned long long wh = *(const unsigned long long*)(bp + n*16);
            unsigned long long wl = *(const unsigned long long*)(bp + TERM + n*16);
            h8[n*2] = (unsigned)wh; h8[n*2+1] = (unsigned)(wh >> 32);
            l8[n*2] = (unsigned)wl; l8[n*2+1] = (unsigned)(wl >> 32);
        }
    };

    for (int ch = 0; ch < 64; ++ch) {
        if (ch == 63) { CP_WAIT0(); } else { CP_WAIT1(); }   // chunk ch landed
        __syncthreads();

        const float* bm = bufs + (ch & 1)*BUFF;
        const float* arow = Af + ch*ROW_W + mrow + alane;

        // A sliding window: win[i] = split(A[8q + 4i]), i=0..7
        unsigned wh8[8], wl8[8];
        #pragma unroll
        for (int i = 0; i < 8; ++i) split2(arow[4*i], wh8[i], wl8[i]);

        unsigned bh[2][8], bl[2][8];
        loadB(bm, 0, bh[0], bl[0]);

        #pragma unroll
        for (int q = 0; q < 8; ++q) {
            const int cur = q & 1, nxt = cur ^ 1;
            if (q < 7) loadB(bm, q + 1, bh[nxt], bl[nxt]);   // B prefetch

            // extract frags from window (register renames)
            unsigned ah[8] = {wh8[0], wh8[2], wh8[1], wh8[3], wh8[4], wh8[6], wh8[5], wh8[7]};
            unsigned al[8] = {wl8[0], wl8[2], wl8[1], wl8[3], wl8[4], wl8[6], wl8[5], wl8[7]};

            // slide window during MMA burst: 2 new values (positions 8q+32, 8q+36)
            if (q < 7) {
                #pragma unroll
                for (int i = 0; i < 6; ++i) { wh8[i] = wh8[i+2]; wl8[i] = wl8[i+2]; }
                split2(arow[8*q + 32], wh8[6], wl8[6]);
                split2(arow[8*q + 36], wh8[7], wl8[7]);
            }

            // pass-major: accumulator chains spaced 8 HMMAs apart
            #pragma unroll
            for (int n = 0; n < 4; ++n) {        // hi*hi
                mma8(acc[0][n], ah,     bh[cur] + n*2);
                mma8(acc[1][n], ah + 4, bh[cur] + n*2);
            }
            #pragma unroll
            for (int n = 0; n < 4; ++n) {        // hi*lo
                mma8(acc[0][n], ah,     bl[cur] + n*2);
                mma8(acc[1][n], ah + 4, bl[cur] + n*2);
            }
            #pragma unroll
            for (int n = 0; n < 4; ++n) {        // lo*hi
                mma8(acc[0][n], al,     bh[cur] + n*2);
                mma8(acc[1][n], al + 4, bh[cur] + n*2);
            }
        }
        __syncthreads();                          // all warps done with buf(ch&1)
        if (ch + 2 < 64) { stageB(ch + 2, bufs + (ch & 1)*BUFF); CP_COMMIT(); }
    }

    // ---- epilogue: acc -> smem corr[g][j] (pad 65), argmax over j ----
    float* corr_s = bufs;
    #pragma unroll
    for (int f = 0; f < 2; ++f)
        #pragma unroll
        for (int n = 0; n < 4; ++n) {
            const int j = mrow + f*16 + (l >> 2);
            const int g = ncol + n*8 + (l & 3)*2;
            corr_s[(g  )*65 + j    ] = acc[f][n][0];
            corr_s[(g+1)*65 + j    ] = acc[f][n][1];
            corr_s[(g  )*65 + j + 8] = acc[f][n][2];
            corr_s[(g+1)*65 + j + 8] = acc[f][n][3];
        }
    __syncthreads();
    if (t < 128) {
        const int g = t;
        const float* row = corr_s + g*65;
        float bv = row[0]; int bj = 0;
        #pragma unroll
        for (int j = 1; j < 64; ++j) {
            float v = row[j];
            if (v > bv) { bv = v; bj = j; }      // strict > : earliest j (jnp.argmax)
        }
        orien[s*BDIM + g] = (float)bj;
        dist[g*BDIM + s]  = 2.0f - 2.0f * (bv / s_norm);
    }
}

// ---------------- Launcher ----------------
extern "C" void kernel_launch(void* const* d_in, const int* in_sizes, int n_in,
                              void* d_out, int out_size)
{
    const float* sat = (const float*)d_in[0];
    const float* grd = (const float*)d_in[1];
    float* out = (float*)d_out;

    cudaMemcpyAsync(out + OFF_SAT, sat, (size_t)BDIM*FEAT*sizeof(float),
                    cudaMemcpyDeviceToDevice);                       // sat echo
    grdsplit_kernel<<<(4096*BDIM)/256, 256>>>(grd, out + OFF_GRD);   // grd split + echo

    cudaFuncSetAttribute(corr_mma_kernel,
                         cudaFuncAttributeMaxDynamicSharedMemorySize, SMEM_BYTES);
    corr_mma_kernel<<<BDIM, 256, SMEM_BYTES>>>(sat, out + OFF_DIST, out + OFF_OR);
}

// round 16
// speedup vs baseline: 1.1324x; 1.1324x over previous
#include <cuda_runtime.h>
#include <cuda_bf16.h>
#include <cstdint>

// ---------------- Problem constants ----------------
#define BDIM 128
#define HDIM 4
#define WDIM 64
#define CDIM 16
#define FEAT (HDIM*WDIM*CDIM)   // 4096

// Output layout (floats): [sat 524288][grd 524288][distance 16384 (g,s)][orien 16384 (s,g)]
#define OFF_SAT   0
#define OFF_GRD   (BDIM*FEAT)
#define OFF_DIST  (2*BDIM*FEAT)
#define OFF_OR    (2*BDIM*FEAT + BDIM*BDIM)

// satC: per s, rows cr=c*4+h (64 rows) of w'=0..126. k = cr*64 + kw.
#define SATC_PER_S 8128
#define ROW_W 127

// ---------------- Static device scratch ----------------
__device__ float g_satCH[BDIM*SATC_PER_S];
__device__ float g_satCL[BDIM*SATC_PER_S];
// grd transposed + (k,k+4) pair-interleaved, in k32 groups of 16 rows:
// idx = ((ch32*16 + q*4 + r)*256) + g*2 + half;  k = ch32*32 + q*8 + r + half*4
__device__ float g_grdH2[4096*BDIM];
__device__ float g_grdL2[4096*BDIM];
__device__ float g_norms[BDIM];

// ---------------- SMEM layout ----------------
constexpr int A_FLOATS = 2*SATC_PER_S;        // 16256 (Ah + Al)
constexpr int TERM     = 16*264;              // 4224 floats: 16 k-pair rows x (128 g-pairs + pad)
constexpr int BUFF     = 2*TERM;              // 8448 floats per k32 chunk buffer (hi+lo)
constexpr int SMEM_BYTES = (A_FLOATS + 4*BUFF)*4;   // 200192 B

// ---------------- PTX helpers (sm_80-baseline only) ----------------
__device__ __forceinline__ void cp16(float* smem_dst, const float* gsrc) {
    unsigned sa = (unsigned)__cvta_generic_to_shared(smem_dst);
    asm volatile("cp.async.cg.shared.global [%0], [%1], 16;\n" :: "r"(sa), "l"(gsrc));
}
#define CP_COMMIT() asm volatile("cp.async.commit_group;\n" ::: "memory")
#define CP_WAIT0()  asm volatile("cp.async.wait_group 0;\n" ::: "memory")
#define CP_WAIT1()  asm volatile("cp.async.wait_group 1;\n" ::: "memory")
#define CP_WAIT2()  asm volatile("cp.async.wait_group 2;\n" ::: "memory")

__device__ __forceinline__ float tf32r(float x) {
    unsigned r;
    asm("cvt.rna.tf32.f32 %0, %1;" : "=r"(r) : "f"(x));
    return __uint_as_float(r);
}
__device__ __forceinline__ void mma8(float* d, const unsigned* a, const unsigned* b) {
    asm("mma.sync.aligned.m16n8k8.row.col.f32.tf32.tf32.f32 "
        "{%0,%1,%2,%3},{%4,%5,%6,%7},{%8,%9},{%0,%1,%2,%3};"
        : "+f"(d[0]), "+f"(d[1]), "+f"(d[2]), "+f"(d[3])
        : "r"(a[0]), "r"(a[1]), "r"(a[2]), "r"(a[3]), "r"(b[0]), "r"(b[1]));
}

// ---------------- Pre-kernels (identical math to R10 pass) ----------------
__global__ void split_kernel(const float* __restrict__ sat,
                             const float* __restrict__ grd,
                             float* __restrict__ grd_echo)
{
    int i = blockIdx.x * 256 + threadIdx.x;
    if (i < BDIM*SATC_PER_S) {
        int s  = i / SATC_PER_S;
        int r  = i - s*SATC_PER_S;
        int c  = r / (HDIM*ROW_W);
        int r2 = r - c*(HDIM*ROW_W);
        int h  = r2 / ROW_W;
        int wp = r2 - h*ROW_W;
        int w  = (wp < WDIM) ? wp : wp - WDIM;      // circular extension
        float v  = __ldg(&sat[((s*HDIM + h)*WDIM + w)*CDIM + c]);
        float hi = __uint_as_float(__float_as_uint(v) & 0xFFFFE000u);
        g_satCH[i] = hi;
        g_satCL[i] = tf32r(v - hi);
    } else {
        int j = i - BDIM*SATC_PER_S;
        if (j < 4096*BDIM) {
            int half = j & 1;
            int g    = (j >> 1) & 127;
            int row  = (j >> 8) & 15;
            int ch   = j >> 12;
            int q = row >> 2, rr = row & 3;
            int kg = ch*32 + q*8 + rr + half*4;
            int c  = kg >> 8, h = (kg >> 6) & 3, kwf = kg & 63;
            int src = ((g*HDIM + h)*WDIM + kwf)*CDIM + c;
            float v  = __ldg(&grd[src]);
            float hi = __uint_as_float(__float_as_uint(v) & 0xFFFFE000u);
            g_grdH2[j] = hi;
            g_grdL2[j] = tf32r(v - hi);
            grd_echo[src] = v;
        }
    }
}
__global__ void norms_kernel(const float* __restrict__ sat, float* __restrict__ sat_echo) {
    __shared__ float sw[8];
    int s = blockIdx.x, t = threadIdx.x;
    float ss = 0.f;
    for (int i = t; i < FEAT; i += 256) {
        float v = __ldg(&sat[s*FEAT + i]);
        sat_echo[s*FEAT + i] = v;
        ss += v*v;
    }
    #pragma unroll
    for (int o = 16; o > 0; o >>= 1) ss += __shfl_down_sync(0xffffffffu, ss, o);
    if ((t & 31) == 0) sw[t >> 5] = ss;
    __syncthreads();
    if (t == 0) {
        float tot = 0.f;
        #pragma unroll
        for (int i = 0; i < 8; ++i) tot += sw[i];
        g_norms[s] = fmaxf(sqrtf(tot), 1e-12f);
    }
}

// ---------------- Main kernel: block per s, 512 threads = 16 warps ----------------
// warp w: mrow=(w&3)*16 (j), ncol=(w>>2)*32 (g). Warp tile m16 n32, full K.
// 128 chunks of k32; 4-buffer cp.async ring; staging for ch+3 interleaved into
// ch's q-loop (hidden under tensor busy); ONE barrier per chunk.
__global__ __launch_bounds__(512, 1)
void corr_mma_kernel(float* __restrict__ dist, float* __restrict__ orien)
{
    extern __shared__ float smem[];
    float* Ah   = smem;
    float* Al   = smem + SATC_PER_S;
    float* bufs = smem + A_FLOATS;

    const int s  = blockIdx.x;
    const int t  = threadIdx.x;
    const int w  = t >> 5;
    const int l  = t & 31;
    const int mrow = (w & 3) * 16;
    const int ncol = (w >> 2) * 32;

    const int alane  = (l >> 2) + (l & 3);
    const int blane2 = (ncol + (l >> 2)) * 2;

    // ---- stage A (once) ----
    {
        const float* aH = g_satCH + s*SATC_PER_S;
        const float* aL = g_satCL + s*SATC_PER_S;
        #pragma unroll
        for (int i = 0; i < 8; ++i) {
            int idx = i*512 + t;
            if (idx < 4064) {
                int term = (idx >= 2032);
                int u = idx - term*2032;
                cp16((term ? Al : Ah) + u*4, (term ? aL : aH) + u*4);
            }
        }
    }
    // full-chunk stage (prologue only): 2048 16B units over 512 threads
    auto stageB = [&](int ch, float* dstbuf) {
        #pragma unroll
        for (int i = 0; i < 4; ++i) {
            int idx = i*512 + t;
            int term = idx >> 10;
            int ru = idx & 1023;
            int row = ru >> 6, u = ru & 63;
            const float* src = (term ? g_grdL2 : g_grdH2) + ch*4096 + row*256 + u*4;
            cp16(dstbuf + term*TERM + row*264 + u*4, src);
        }
    };
    stageB(0, bufs);          CP_COMMIT();     // group: A + chunk0
    stageB(1, bufs + BUFF);   CP_COMMIT();
    stageB(2, bufs + 2*BUFF); CP_COMMIT();

    float acc[4][4];
    #pragma unroll
    for (int n = 0; n < 4; ++n)
        #pragma unroll
        for (int r = 0; r < 4; ++r) acc[n][r] = 0.f;

    auto loadA = [&](int ai, unsigned* a4, unsigned* b4) {
        a4[0] = __float_as_uint(Ah[ai     ]);
        a4[1] = __float_as_uint(Ah[ai +  8]);
        a4[2] = __float_as_uint(Ah[ai +  4]);
        a4[3] = __float_as_uint(Ah[ai + 12]);
        b4[0] = __float_as_uint(Al[ai     ]);
        b4[1] = __float_as_uint(Al[ai +  8]);
        b4[2] = __float_as_uint(Al[ai +  4]);
        b4[3] = __float_as_uint(Al[ai + 12]);
    };
    auto loadB = [&](const float* bm, int q, unsigned* h8, unsigned* l8) {
        const float* bp = bm + (q*4 + (l & 3))*264 + blane2;
        #pragma unroll
        for (int n = 0; n < 4; ++n) {
            unsigned long long wh = *(const unsigned long long*)(bp + n*16);
            unsigned long long wl = *(const unsigned long long*)(bp + TERM + n*16);
            h8[n*2] = (unsigned)wh; h8[n*2+1] = (unsigned)(wh >> 32);
            l8[n*2] = (unsigned)wl; l8[n*2+1] = (unsigned)(wl >> 32);
        }
    };

    for (int ch = 0; ch < 128; ++ch) {
        if (ch < 126) { CP_WAIT2(); } else if (ch == 126) { CP_WAIT1(); } else { CP_WAIT0(); }
        __syncthreads();                              // chunk ch visible; ch-1 readers done

        const float* bm = bufs + (ch & 3)*BUFF;
        const int abase = (ch >> 1)*ROW_W + (ch & 1)*32 + mrow + alane;
        const bool doStage = (ch + 3 < 128);
        float* dstb = bufs + ((ch + 3) & 3)*BUFF;     // ring: not read by ch or ch+1/ch+2
        const int ch3 = ch + 3;

        unsigned ah[2][4], al[2][4], bh[2][8], bl[2][8];
        loadA(abase, ah[0], al[0]);
        loadB(bm, 0, bh[0], bl[0]);

        #pragma unroll
        for (int q = 0; q < 4; ++q) {
            const int cur = q & 1, nxt = cur ^ 1;
            if (doStage) {                            // 1 cp16/thread/q: hides under MMAs
                int idx = q*512 + t;
                int term = idx >> 10;
                int ru = idx & 1023;
                int row = ru >> 6, u = ru & 63;
                cp16(dstb + term*TERM + row*264 + u*4,
                     (term ? g_grdL2 : g_grdH2) + ch3*4096 + row*256 + u*4);
            }
            if (q < 3) {                              // frag prefetch
                loadA(abase + 8*(q + 1), ah[nxt], al[nxt]);
                loadB(bm, q + 1, bh[nxt], bl[nxt]);
            }
            // pass-major: accumulator chains spaced 4 HMMAs apart
            #pragma unroll
            for (int n = 0; n < 4; ++n) mma8(acc[n], ah[cur], bh[cur] + n*2);   // hi*hi
            #pragma unroll
            for (int n = 0; n < 4; ++n) mma8(acc[n], ah[cur], bl[cur] + n*2);   // hi*lo
            #pragma unroll
            for (int n = 0; n < 4; ++n) mma8(acc[n], al[cur], bh[cur] + n*2);   // lo*hi
        }
        if (doStage) CP_COMMIT();
    }
    __syncthreads();                                  // all reads of bufs done

    // ---- epilogue: acc -> smem corr[g][j] (pad 65), argmax over j ----
    float* corr_s = bufs;
    #pragma unroll
    for (int n = 0; n < 4; ++n) {
        const int j = mrow + (l >> 2);
        const int g = ncol + n*8 + (l & 3)*2;
        corr_s[(g  )*65 + j    ] = acc[n][0];
        corr_s[(g+1)*65 + j    ] = acc[n][1];
        corr_s[(g  )*65 + j + 8] = acc[n][2];
        corr_s[(g+1)*65 + j + 8] = acc[n][3];
    }
    __syncthreads();
    if (t < 128) {
        const int g = t;
        const float* row = corr_s + g*65;
        float bv = row[0]; int bj = 0;
        #pragma unroll
        for (int j = 1; j < 64; ++j) {
            float v = row[j];
            if (v > bv) { bv = v; bj = j; }           // strict > : earliest j (jnp.argmax)
        }
        orien[s*BDIM + g] = (float)bj;
        dist[g*BDIM + s]  = 2.0f - 2.0f * (bv / g_norms[s]);
    }
}

// ---------------- Launcher ----------------
extern "C" void kernel_launch(void* const* d_in, const int* in_sizes, int n_in,
                              void* d_out, int out_size)
{
    const float* sat = (const float*)d_in[0];
    const float* grd = (const float*)d_in[1];
    float* out = (float*)d_out;

    const int total = BDIM*SATC_PER_S + 4096*BDIM;
    split_kernel<<<(total + 255)/256, 256>>>(sat, grd, out + OFF_GRD);
    norms_kernel<<<BDIM, 256>>>(sat, out + OFF_SAT);

    cudaFuncSetAttribute(corr_mma_kernel,
                         cudaFuncAttributeMaxDynamicSharedMemorySize, SMEM_BYTES);
    corr_mma_kernel<<<BDIM, 512, SMEM_BYTES>>>(out + OFF_DIST, out + OFF_OR);
}

// round 17
// speedup vs baseline: 1.3668x; 1.2070x over previous
#include <cuda_runtime.h>
#include <cuda_bf16.h>
#include <cstdint>

// ---------------- Problem constants ----------------
#define BDIM 128
#define HDIM 4
#define WDIM 64
#define CDIM 16
#define FEAT (HDIM*WDIM*CDIM)   // 4096

// Output layout (floats): [sat 524288][grd 524288][distance 16384 (g,s)][orien 16384 (s,g)]
#define OFF_SAT   0
#define OFF_GRD   (BDIM*FEAT)
#define OFF_DIST  (2*BDIM*FEAT)
#define OFF_OR    (2*BDIM*FEAT + BDIM*BDIM)

// satC: per s, rows cr=c*4+h (64 rows) of w'=0..126. k = cr*64 + kw.
#define SATC_PER_S 8128
#define ROW_W 127

// ---------------- Static device scratch ----------------
__device__ float g_satCH[BDIM*SATC_PER_S];              // tf32-hi fp32
__device__ __nv_bfloat16 g_satHb [BDIM*SATC_PER_S];     // bf16(hi)
__device__ __nv_bfloat16 g_satHbs[BDIM*SATC_PER_S];     // bf16(hi) shifted by 1
__device__ __nv_bfloat16 g_satLb [BDIM*SATC_PER_S];     // bf16(lo)
__device__ __nv_bfloat16 g_satLbs[BDIM*SATC_PER_S];     // bf16(lo) shifted by 1
// fp32 hi grd, (k,k+4) pair-interleaved per k32 group (proven layout):
// idx = ((ch*16 + q*4 + r)*256) + g*2 + half;  k = ch*32 + q*8 + r + half*4
__device__ float g_grdH2[4096*BDIM];
// bf16 grd, k16-frag interleaved: u32 j = ((ch*8 + p*4 + cq)*128 + g)*2 + hi8
// holds bf16 pair {B[k0],B[k0+1]} with k0 = ch*32 + p*16 + 2cq + hi8*8
__device__ unsigned g_grdBh[4096*BDIM/2];
__device__ unsigned g_grdBl[4096*BDIM/2];
__device__ float g_norms[BDIM];

// ---------------- SMEM layout (floats) ----------------
constexpr int AH_OFF   = 0;          // 8128 fp32
constexpr int AHB_OFF  = 8128;       // 4064 (8128 bf16)
constexpr int AHBS_OFF = 12192;      // 4064
constexpr int ALB_OFF  = 16256;      // 4064
constexpr int ALBS_OFF = 20320;      // 4064
constexpr int BUF_OFF  = 24384;
// per chunk buffer: fp32 Bh 16 rows x 264 = 4224 | bf16 2 terms x 8 rows x 264 = 4224
constexpr int BUFF     = 8448;
constexpr int SMEM_BYTES = (BUF_OFF + 3*BUFF)*4;   // 198912 B

// ---------------- PTX helpers (sm_80-baseline only) ----------------
__device__ __forceinline__ void cp16(float* smem_dst, const float* gsrc) {
    unsigned sa = (unsigned)__cvta_generic_to_shared(smem_dst);
    asm volatile("cp.async.cg.shared.global [%0], [%1], 16;\n" :: "r"(sa), "l"(gsrc));
}
#define CP_COMMIT() asm volatile("cp.async.commit_group;\n" ::: "memory")
#define CP_WAIT0()  asm volatile("cp.async.wait_group 0;\n" ::: "memory")
#define CP_WAIT1()  asm volatile("cp.async.wait_group 1;\n" ::: "memory")

__device__ __forceinline__ float tf32r(float x) {
    unsigned r;
    asm("cvt.rna.tf32.f32 %0, %1;" : "=r"(r) : "f"(x));
    return __uint_as_float(r);
}
__device__ __forceinline__ void mma8(float* d, const unsigned* a, const unsigned* b) {
    asm("mma.sync.aligned.m16n8k8.row.col.f32.tf32.tf32.f32 "
        "{%0,%1,%2,%3},{%4,%5,%6,%7},{%8,%9},{%0,%1,%2,%3};"
        : "+f"(d[0]), "+f"(d[1]), "+f"(d[2]), "+f"(d[3])
        : "r"(a[0]), "r"(a[1]), "r"(a[2]), "r"(a[3]), "r"(b[0]), "r"(b[1]));
}
__device__ __forceinline__ void mma16(float* d, const unsigned* a, const unsigned* b) {
    asm("mma.sync.aligned.m16n8k16.row.col.f32.bf16.bf16.f32 "
        "{%0,%1,%2,%3},{%4,%5,%6,%7},{%8,%9},{%0,%1,%2,%3};"
        : "+f"(d[0]), "+f"(d[1]), "+f"(d[2]), "+f"(d[3])
        : "r"(a[0]), "r"(a[1]), "r"(a[2]), "r"(a[3]), "r"(b[0]), "r"(b[1]));
}
__device__ __forceinline__ unsigned pk(float lo, float hi) {
    __nv_bfloat162 t = __floats2bfloat162_rn(lo, hi);   // .x = lo bits
    return *(unsigned*)&t;
}

// ---------------- Pre-kernels ----------------
constexpr int N1 = BDIM*SATC_PER_S;    // 1040384  sat split
constexpr int N2 = 4096*BDIM;          // 524288   grd fp32 + echo
constexpr int N3 = 4096*BDIM/2;        // 262144   grd bf16
__global__ void split_kernel(const float* __restrict__ sat,
                             const float* __restrict__ grd,
                             float* __restrict__ grd_echo)
{
    int i = blockIdx.x * 256 + threadIdx.x;
    if (i < N1) {
        int s  = i / SATC_PER_S;
        int r  = i - s*SATC_PER_S;
        int c  = r / (HDIM*ROW_W);
        int r2 = r - c*(HDIM*ROW_W);
        int h  = r2 / ROW_W;
        int wp = r2 - h*ROW_W;
        int w  = (wp < WDIM) ? wp : wp - WDIM;      // circular extension
        float v  = __ldg(&sat[((s*HDIM + h)*WDIM + w)*CDIM + c]);
        float hi = __uint_as_float(__float_as_uint(v) & 0xFFFFE000u);
        float lo = tf32r(v - hi);
        g_satCH[i] = hi;
        g_satHb[i] = __float2bfloat16(hi);
        g_satLb[i] = __float2bfloat16(lo);
        if (r > 0) {
            g_satHbs[i-1] = __float2bfloat16(hi);
            g_satLbs[i-1] = __float2bfloat16(lo);
        }
    } else if (i < N1 + N2) {
        int j = i - N1;
        int half = j & 1;
        int g    = (j >> 1) & 127;
        int row  = (j >> 8) & 15;
        int ch   = j >> 12;
        int q = row >> 2, rr = row & 3;
        int kg = ch*32 + q*8 + rr + half*4;
        int c  = kg >> 8, h = (kg >> 6) & 3, kwf = kg & 63;
        int src = ((g*HDIM + h)*WDIM + kwf)*CDIM + c;
        float v  = __ldg(&grd[src]);
        g_grdH2[j] = __uint_as_float(__float_as_uint(v) & 0xFFFFE000u);
        grd_echo[src] = v;
    } else if (i < N1 + N2 + N3) {
        int j = i - N1 - N2;                 // output u32 index
        int hi8 = j & 1;
        int g   = (j >> 1) & 127;
        int rc  = j >> 8;                    // ch*8 + p*4 + cq
        int cq  = rc & 3, p = (rc >> 2) & 1, ch = rc >> 3;
        int k0  = ch*32 + p*16 + 2*cq + hi8*8;
        float h2[2], l2[2];
        #pragma unroll
        for (int e = 0; e < 2; ++e) {
            int k = k0 + e;
            int c = k >> 8, h = (k >> 6) & 3, kwf = k & 63;
            float v  = __ldg(&grd[((g*HDIM + h)*WDIM + kwf)*CDIM + c]);
            float hi = __uint_as_float(__float_as_uint(v) & 0xFFFFE000u);
            h2[e] = hi;
            l2[e] = tf32r(v - hi);
        }
        g_grdBh[j] = pk(h2[0], h2[1]);
        g_grdBl[j] = pk(l2[0], l2[1]);
    }
}
__global__ void norms_kernel(const float* __restrict__ sat, float* __restrict__ sat_echo) {
    __shared__ float sw[8];
    int s = blockIdx.x, t = threadIdx.x;
    float ss = 0.f;
    for (int i = t; i < FEAT; i += 256) {
        float v = __ldg(&sat[s*FEAT + i]);
        sat_echo[s*FEAT + i] = v;
        ss += v*v;
    }
    #pragma unroll
    for (int o = 16; o > 0; o >>= 1) ss += __shfl_down_sync(0xffffffffu, ss, o);
    if ((t & 31) == 0) sw[t >> 5] = ss;
    __syncthreads();
    if (t == 0) {
        float tot = 0.f;
        #pragma unroll
        for (int i = 0; i < 8; ++i) tot += sw[i];
        g_norms[s] = fmaxf(sqrtf(tot), 1e-12f);
    }
}

// ---------------- Main kernel: block per s, 256 threads = 8 warps ----------------
// warp w: mrow=(w&1)*32 (j), ncol=(w>>1)*32 (g). m32n32 warp tile, full K.
// 128 chunks of k32; 3-buffer cp.async ring, ONE barrier per chunk.
// Per chunk: tf32 hi*hi (4q x 8 MMA) + bf16 corrections Ah*Bl + Al*Bh (2p x 16 MMA).
__global__ __launch_bounds__(256, 1)
void corr_mma_kernel(float* __restrict__ dist, float* __restrict__ orien)
{
    extern __shared__ float smem[];
    float* Ah   = smem + AH_OFF;
    float* bufs = smem + BUF_OFF;
    const unsigned* AhbU  = (const unsigned*)(smem + AHB_OFF);
    const unsigned* AhbSU = (const unsigned*)(smem + AHBS_OFF);
    const unsigned* AlbU  = (const unsigned*)(smem + ALB_OFF);
    const unsigned* AlbSU = (const unsigned*)(smem + ALBS_OFF);

    const int s  = blockIdx.x;
    const int t  = threadIdx.x;
    const int w  = t >> 5;
    const int l  = t & 31;
    const int mrow = (w & 1) * 32;
    const int ncol = (w >> 1) * 32;
    const int lr = l >> 2, lc = l & 3;

    const int alane  = lr + lc;
    const int blane2 = (ncol + lr) * 2;

    // ---- stage A (fp32 + 4 bf16 arrays) via cp.async, group 0 with chunk 0 ----
    {
        float* dstArr[4] = {smem+AHB_OFF, smem+AHBS_OFF, smem+ALB_OFF, smem+ALBS_OFF};
        const float* srcArr[4] = {
            (const float*)(g_satHb  + s*SATC_PER_S), (const float*)(g_satHbs + s*SATC_PER_S),
            (const float*)(g_satLb  + s*SATC_PER_S), (const float*)(g_satLbs + s*SATC_PER_S)};
        #pragma unroll
        for (int it = 0; it < 24; ++it) {
            int idx = it*256 + t;
            if (idx < 2032) {
                cp16(Ah + idx*4, g_satCH + s*SATC_PER_S + idx*4);
            } else if (idx < 6096) {
                int j = idx - 2032;
                int a = j / 1016, u = j - a*1016;
                cp16(dstArr[a] + u*4, srcArr[a] + u*4);
            }
        }
    }
    // stage one k32 chunk: fp32 1024 cp16 + bf16 1024 cp16 = 8/thread
    auto stage = [&](int ch, float* dstbuf) {
        #pragma unroll
        for (int i = 0; i < 8; ++i) {
            int idx = i*256 + t;
            if (idx < 1024) {                                  // fp32: 16 rows x 64
                int row = idx >> 6, u = idx & 63;
                cp16(dstbuf + row*264 + u*4, g_grdH2 + ch*4096 + row*256 + u*4);
            } else {                                           // bf16: 2T x 8 rows x 64
                int j2 = idx - 1024;
                int T = j2 >> 9, ru = j2 & 511, row = ru >> 6, u = ru & 63;
                const float* src = (const float*)(T ? g_grdBl : g_grdBh)
                                   + ch*2048 + row*256 + u*4;
                cp16(dstbuf + 4224 + T*2112 + row*264 + u*4, src);
            }
        }
    };
    stage(0, bufs);        CP_COMMIT();     // group: A + chunk0
    stage(1, bufs + BUFF); CP_COMMIT();

    float acc[2][4][4];
    #pragma unroll
    for (int f = 0; f < 2; ++f)
        #pragma unroll
        for (int n = 0; n < 4; ++n)
            #pragma unroll
            for (int r = 0; r < 4; ++r) acc[f][n][r] = 0.f;

    auto loadAh = [&](int ai, unsigned* a8) {
        a8[0] = __float_as_uint(Ah[ai     ]);
        a8[1] = __float_as_uint(Ah[ai +  8]);
        a8[2] = __float_as_uint(Ah[ai +  4]);
        a8[3] = __float_as_uint(Ah[ai + 12]);
        a8[4] = __float_as_uint(Ah[ai + 16]);
        a8[5] = __float_as_uint(Ah[ai + 24]);
        a8[6] = __float_as_uint(Ah[ai + 20]);
        a8[7] = __float_as_uint(Ah[ai + 28]);
    };
    auto loadBh = [&](const float* bm, int q, unsigned* h8) {
        const float* bp = bm + (q*4 + lc)*264 + blane2;
        #pragma unroll
        for (int n = 0; n < 4; ++n) {
            unsigned long long wh = *(const unsigned long long*)(bp + n*16);
            h8[n*2] = (unsigned)wh; h8[n*2+1] = (unsigned)(wh >> 32);
        }
    };

    for (int ch = 0; ch < 128; ++ch) {
        if (ch < 127) { CP_WAIT1(); } else { CP_WAIT0(); }   // chunk ch landed
        __syncthreads();                                      // visible; ch-1 readers done
        if (ch + 2 < 128) { stage(ch + 2, bufs + ((ch + 2) % 3)*BUFF); CP_COMMIT(); }

        const float* bm = bufs + (ch % 3)*BUFF;
        const int cr = ch >> 1, kw0 = (ch & 1)*32;
        const int abase = cr*ROW_W + kw0 + mrow + alane;

        // ---- tf32 pass: hi*hi, 4 q-steps of k8, frag ping-pong ----
        unsigned ah[2][8], bh[2][8];
        loadAh(abase, ah[0]);
        loadBh(bm, 0, bh[0]);
        #pragma unroll
        for (int q = 0; q < 4; ++q) {
            const int cur = q & 1, nxt = cur ^ 1;
            if (q < 3) { loadAh(abase + 8*(q+1), ah[nxt]); loadBh(bm, q+1, bh[nxt]); }
            #pragma unroll
            for (int n = 0; n < 4; ++n) mma8(acc[0][n], ah[cur],     bh[cur] + n*2);
            #pragma unroll
            for (int n = 0; n < 4; ++n) mma8(acc[1][n], ah[cur] + 4, bh[cur] + n*2);
        }

        // ---- bf16 correction passes: Ah*Bl + Al*Bh, 2 p-steps of k16 ----
        const int par = (cr + lr) & 1;                       // element parity of A index
        const unsigned* AHp = par ? AhbSU : AhbU;
        const unsigned* ALp = par ? AlbSU : AlbU;
        const int eb = cr*ROW_W + kw0 + mrow + lr + 2*lc;    // element idx (p=0,f=0)
        const int ub = (eb - par) >> 1;                      // u32 index
        #pragma unroll
        for (int p = 0; p < 2; ++p) {
            unsigned LH[5], LL[5];
            #pragma unroll
            for (int i = 0; i < 5; ++i) {
                LH[i] = AHp[ub + p*8 + 4*i];
                LL[i] = ALp[ub + p*8 + 4*i];
            }
            unsigned bhb[8], blb[8];
            const float* bbp = bm + 4224 + (p*4 + lc)*264 + blane2;
            #pragma unroll
            for (int n = 0; n < 4; ++n) {
                unsigned long long wh = *(const unsigned long long*)(bbp + n*16);
                unsigned long long wl = *(const unsigned long long*)(bbp + 2112 + n*16);
                bhb[n*2] = (unsigned)wh; bhb[n*2+1] = (unsigned)(wh >> 32);
                blb[n*2] = (unsigned)wl; blb[n*2+1] = (unsigned)(wl >> 32);
            }
            // circulant overlap: a1==a2, and f1's a0 == f0's a3
            unsigned a0h[4] = {LH[0], LH[1], LH[1], LH[2]};
            unsigned a1h[4] = {LH[2], LH[3], LH[3], LH[4]};
            unsigned a0l[4] = {LL[0], LL[1], LL[1], LL[2]};
            unsigned a1l[4] = {LL[2], LL[3], LL[3], LL[4]};
            #pragma unroll
            for (int n = 0; n < 4; ++n) mma16(acc[0][n], a0h, blb + n*2);   // Ah*Bl
            #pragma unroll
            for (int n = 0; n < 4; ++n) mma16(acc[1][n], a1h, blb + n*2);
            #pragma unroll
            for (int n = 0; n < 4; ++n) mma16(acc[0][n], a0l, bhb + n*2);   // Al*Bh
            #pragma unroll
            for (int n = 0; n < 4; ++n) mma16(acc[1][n], a1l, bhb + n*2);
        }
    }
    __syncthreads();                                  // all reads of bufs done

    // ---- epilogue: acc -> smem corr[g][j] (pad 65), argmax over j ----
    float* corr_s = bufs;
    #pragma unroll
    for (int f = 0; f < 2; ++f)
        #pragma unroll
        for (int n = 0; n < 4; ++n) {
            const int j = mrow + f*16 + lr;
            const int g = ncol + n*8 + lc*2;
            corr_s[(g  )*65 + j    ] = acc[f][n][0];
            corr_s[(g+1)*65 + j    ] = acc[f][n][1];
            corr_s[(g  )*65 + j + 8] = acc[f][n][2];
            corr_s[(g+1)*65 + j + 8] = acc[f][n][3];
        }
    __syncthreads();
    if (t < 128) {
        const int g = t;
        const float* row = corr_s + g*65;
        float bv = row[0]; int bj = 0;
        #pragma unroll
        for (int j = 1; j < 64; ++j) {
            float v = row[j];
            if (v > bv) { bv = v; bj = j; }           // strict > : earliest j (jnp.argmax)
        }
        orien[s*BDIM + g] = (float)bj;
        dist[g*BDIM + s]  = 2.0f - 2.0f * (bv / g_norms[s]);
    }
}

// ---------------- Launcher ----------------
extern "C" void kernel_launch(void* const* d_in, const int* in_sizes, int n_in,
                              void* d_out, int out_size)
{
    const float* sat = (const float*)d_in[0];
    const float* grd = (const float*)d_in[1];
    float* out = (float*)d_out;

    const int total = N1 + N2 + N3;
    split_kernel<<<(total + 255)/256, 256>>>(sat, grd, out + OFF_GRD);
    norms_kernel<<<BDIM, 256>>>(sat, out + OFF_SAT);

    cudaFuncSetAttribute(corr_mma_kernel,
                         cudaFuncAttributeMaxDynamicSharedMemorySize, SMEM_BYTES);
    corr_mma_kernel<<<BDIM, 256, SMEM_BYTES>>>(out + OFF_DIST, out + OFF_OR);
}